// round 2
// baseline (speedup 1.0000x reference)
#include <cuda_runtime.h>

// Problem constants
#define BB 4
#define LL 512
#define DD 1024
#define HH 16
#define DH 64
#define BH (BB*HH)            // 64
#define OUT_ELEMS (BB*LL*DD)  // 2097152

// Scratch (no allocations allowed -> __device__ globals)
__device__ float g_q[BB*HH*LL*DH];
__device__ float g_k[BB*HH*LL*DH];
__device__ float g_v[BB*HH*LL*DH];
__device__ float g_ctx[BB*LL*DD];

// ---------------------------------------------------------------------------
// K1/K6: C = A(2048x1024) @ W(1024x1024) + bias, optional scale, two output
// layouts: mode 0 -> plain [m][n]; mode 1 -> [b][h][l][dh] (b=m/512,l=m%512,
// h=n/64,dh=n%64). 128x128 tile, BK=16, 256 threads, 8x8 per thread.
// ---------------------------------------------------------------------------
__global__ __launch_bounds__(256) void sgemm_proj(
    const float* __restrict__ A, const float* __restrict__ W,
    const float* __restrict__ bias, float* __restrict__ out,
    float scale, int mode)
{
    const int M = 2048, N = 1024, K = 1024;
    __shared__ float As[16][132];   // k-major (transposed), padded
    __shared__ float Bs[16][128];

    int t  = threadIdx.x;
    int m0 = blockIdx.y * 128;
    int n0 = blockIdx.x * 128;
    int ty = t >> 4, tx = t & 15;

    int arow = t >> 2;          // 0..63
    int acg  = (t & 3) * 4;     // k offset within tile
    int brow = t >> 5;          // 0..7
    int bcg  = (t & 31) * 4;

    float acc[8][8];
    #pragma unroll
    for (int i = 0; i < 8; i++)
        #pragma unroll
        for (int j = 0; j < 8; j++) acc[i][j] = 0.f;

    for (int k0 = 0; k0 < K; k0 += 16) {
        #pragma unroll
        for (int rr = 0; rr < 2; rr++) {
            int r = arow + rr * 64;
            float4 va = *(const float4*)&A[(size_t)(m0 + r) * K + k0 + acg];
            As[acg + 0][r] = va.x; As[acg + 1][r] = va.y;
            As[acg + 2][r] = va.z; As[acg + 3][r] = va.w;
        }
        #pragma unroll
        for (int rr = 0; rr < 2; rr++) {
            int r = brow + rr * 8;
            *(float4*)&Bs[r][bcg] = *(const float4*)&W[(size_t)(k0 + r) * N + n0 + bcg];
        }
        __syncthreads();
        #pragma unroll
        for (int kk = 0; kk < 16; kk++) {
            float a[8], b[8];
            *(float4*)&a[0] = *(const float4*)&As[kk][ty * 8];
            *(float4*)&a[4] = *(const float4*)&As[kk][ty * 8 + 4];
            *(float4*)&b[0] = *(const float4*)&Bs[kk][tx * 8];
            *(float4*)&b[4] = *(const float4*)&Bs[kk][tx * 8 + 4];
            #pragma unroll
            for (int i = 0; i < 8; i++)
                #pragma unroll
                for (int j = 0; j < 8; j++)
                    acc[i][j] += a[i] * b[j];
        }
        __syncthreads();
    }

    #pragma unroll
    for (int i = 0; i < 8; i++) {
        int m = m0 + ty * 8 + i;
        int b = m >> 9, l = m & 511;
        #pragma unroll
        for (int j = 0; j < 8; j++) {
            int n = n0 + tx * 8 + j;
            float v = (acc[i][j] + bias[n]) * scale;
            if (mode) {
                int h = n >> 6, dh = n & 63;
                out[(((size_t)(b * HH + h) * LL + l) * DH) + dh] = v;
            } else {
                out[(size_t)m * N + n] = v;
            }
        }
    }
}

// ---------------------------------------------------------------------------
// K2: scores[bh][i][j] = q[bh][i][:] . k[bh][j][:]   (M=N=512, K=64 per bh)
// 128x128 tile, BK=16, both operands transposed into smem.
// ---------------------------------------------------------------------------
__global__ __launch_bounds__(256) void qk_kernel(float* __restrict__ scores)
{
    __shared__ float As[16][132];
    __shared__ float Bs[16][132];

    int t  = threadIdx.x;
    int bh = blockIdx.z;
    const float* Q  = g_q + (size_t)bh * LL * DH;
    const float* Km = g_k + (size_t)bh * LL * DH;
    int m0 = blockIdx.y * 128, n0 = blockIdx.x * 128;
    int ty = t >> 4, tx = t & 15;
    int lrow = t >> 2;
    int lk   = (t & 3) * 4;

    float acc[8][8];
    #pragma unroll
    for (int i = 0; i < 8; i++)
        #pragma unroll
        for (int j = 0; j < 8; j++) acc[i][j] = 0.f;

    for (int k0 = 0; k0 < DH; k0 += 16) {
        #pragma unroll
        for (int rr = 0; rr < 2; rr++) {
            int r = lrow + rr * 64;
            float4 va = *(const float4*)&Q[(size_t)(m0 + r) * DH + k0 + lk];
            As[lk + 0][r] = va.x; As[lk + 1][r] = va.y;
            As[lk + 2][r] = va.z; As[lk + 3][r] = va.w;
            float4 vb = *(const float4*)&Km[(size_t)(n0 + r) * DH + k0 + lk];
            Bs[lk + 0][r] = vb.x; Bs[lk + 1][r] = vb.y;
            Bs[lk + 2][r] = vb.z; Bs[lk + 3][r] = vb.w;
        }
        __syncthreads();
        #pragma unroll
        for (int kk = 0; kk < 16; kk++) {
            float a[8], b[8];
            *(float4*)&a[0] = *(const float4*)&As[kk][ty * 8];
            *(float4*)&a[4] = *(const float4*)&As[kk][ty * 8 + 4];
            *(float4*)&b[0] = *(const float4*)&Bs[kk][tx * 8];
            *(float4*)&b[4] = *(const float4*)&Bs[kk][tx * 8 + 4];
            #pragma unroll
            for (int i = 0; i < 8; i++)
                #pragma unroll
                for (int j = 0; j < 8; j++)
                    acc[i][j] += a[i] * b[j];
        }
        __syncthreads();
    }

    float* srow = scores + (size_t)bh * LL * LL;
    #pragma unroll
    for (int i = 0; i < 8; i++) {
        int m = m0 + ty * 8 + i;
        #pragma unroll
        for (int j = 0; j < 8; j++)
            srow[(size_t)m * LL + n0 + tx * 8 + j] = acc[i][j];
    }
}

// ---------------------------------------------------------------------------
// K3: scores[b][h][i][j] += q[b][h][i][:] . emb(matrix[b][i][j])[:]
// emb = struct_emb if j even else value_emb. One block per (i, b),
// 128 threads; j tiled by 128; per thread 4 h x 4 j micro-tile.
// ---------------------------------------------------------------------------
__global__ __launch_bounds__(128) void ast_kernel(
    const int* __restrict__ mat, const float* __restrict__ semb,
    const float* __restrict__ vemb, float* __restrict__ scores)
{
    __shared__ float qs[16][68];
    __shared__ float pe[128][68];
    __shared__ float sc[16][132];

    int i = blockIdx.x, b = blockIdx.y;
    int t = threadIdx.x;

    for (int idx = t; idx < HH * DH; idx += 128) {
        int h = idx >> 6, d = idx & 63;
        qs[h][d] = g_q[(((size_t)(b * HH + h) * LL + i) * DH) + d];
    }

    const int* mrow = mat + (size_t)(b * LL + i) * LL;
    int hg = t & 3;      // h = hg + 4*hh
    int j4 = t >> 2;     // 0..31 -> j = j0 + j4*4 + jj

    for (int jt = 0; jt < 4; jt++) {
        int j0 = jt * 128;
        __syncthreads();   // protect pe/sc reuse + first-iter qs visibility
        {
            int j  = j0 + t;
            int id = mrow[j];
            const float* e = ((j & 1) ? vemb : semb) + (size_t)id * DH;
            #pragma unroll
            for (int s = 0; s < 64; s += 4)
                *(float4*)&pe[t][s] = *(const float4*)&e[s];
        }
        __syncthreads();

        float acc[4][4];
        #pragma unroll
        for (int a = 0; a < 4; a++)
            #pragma unroll
            for (int c = 0; c < 4; c++) acc[a][c] = 0.f;

        #pragma unroll
        for (int d4 = 0; d4 < 16; d4++) {
            float4 q4[4], p4[4];
            #pragma unroll
            for (int hh = 0; hh < 4; hh++)
                q4[hh] = *(const float4*)&qs[hg + 4 * hh][d4 * 4];
            #pragma unroll
            for (int jj = 0; jj < 4; jj++)
                p4[jj] = *(const float4*)&pe[j4 * 4 + jj][d4 * 4];
            #pragma unroll
            for (int hh = 0; hh < 4; hh++)
                #pragma unroll
                for (int jj = 0; jj < 4; jj++) {
                    acc[hh][jj] += q4[hh].x * p4[jj].x;
                    acc[hh][jj] += q4[hh].y * p4[jj].y;
                    acc[hh][jj] += q4[hh].z * p4[jj].z;
                    acc[hh][jj] += q4[hh].w * p4[jj].w;
                }
        }

        #pragma unroll
        for (int hh = 0; hh < 4; hh++)
            #pragma unroll
            for (int jj = 0; jj < 4; jj++)
                sc[hg + 4 * hh][j4 * 4 + jj] = acc[hh][jj];
        __syncthreads();

        for (int idx = t; idx < HH * 128; idx += 128) {
            int h = idx >> 7, j = idx & 127;
            scores[(((size_t)(b * HH + h) * LL + i) * LL) + j0 + j] += sc[h][j];
        }
    }
}

// ---------------------------------------------------------------------------
// K4: in-place masked softmax over last dim (512). One block (128 thr) per row.
// ---------------------------------------------------------------------------
__global__ __launch_bounds__(128) void softmax_kernel(
    float* __restrict__ attn, const unsigned char* __restrict__ mask)
{
    int row = blockIdx.x;              // (b*H + h)*L + i
    int b   = row >> 13;               // / (H*L)
    int t   = threadIdx.x;
    size_t base = (size_t)row * LL + t * 4;

    float4 s = *(float4*)&attn[base];
    const unsigned char* mk = mask + b * LL + t * 4;
    if (mk[0]) s.x = -1e18f;
    if (mk[1]) s.y = -1e18f;
    if (mk[2]) s.z = -1e18f;
    if (mk[3]) s.w = -1e18f;

    float mx = fmaxf(fmaxf(s.x, s.y), fmaxf(s.z, s.w));
    #pragma unroll
    for (int o = 16; o > 0; o >>= 1)
        mx = fmaxf(mx, __shfl_xor_sync(0xffffffffu, mx, o));

    __shared__ float red[8];
    int w = t >> 5, ln = t & 31;
    if (ln == 0) red[w] = mx;
    __syncthreads();
    mx = fmaxf(fmaxf(red[0], red[1]), fmaxf(red[2], red[3]));

    float e0 = __expf(s.x - mx);
    float e1 = __expf(s.y - mx);
    float e2 = __expf(s.z - mx);
    float e3 = __expf(s.w - mx);
    float sm = e0 + e1 + e2 + e3;
    #pragma unroll
    for (int o = 16; o > 0; o >>= 1)
        sm += __shfl_xor_sync(0xffffffffu, sm, o);
    if (ln == 0) red[4 + w] = sm;
    __syncthreads();
    sm = red[4] + red[5] + red[6] + red[7];

    float inv = 1.0f / sm;
    s.x = e0 * inv; s.y = e1 * inv; s.z = e2 * inv; s.w = e3 * inv;
    *(float4*)&attn[base] = s;
}

// ---------------------------------------------------------------------------
// K5: ctx[b][i][h*64+d] = sum_j attn[bh][i][j] * v[bh][j][d]
// per bh: M=512, N=64, K=512. BM=64, BN=64, BK=32, 256 threads, 4x4/thread.
// ---------------------------------------------------------------------------
__global__ __launch_bounds__(256) void av_kernel(
    const float* __restrict__ attn, float* __restrict__ ctx)
{
    __shared__ float As[32][68];
    __shared__ float Bs[32][64];

    int t  = threadIdx.x;
    int bh = blockIdx.y;
    int m0 = blockIdx.x * 64;
    const float* A = attn + (size_t)bh * LL * LL;
    const float* V = g_v + (size_t)bh * LL * DH;
    int ty = t >> 4, tx = t & 15;

    int ar = t >> 3;        // 0..31
    int ac = (t & 7) * 4;
    int br = t >> 4;        // 0..15
    int bc = (t & 15) * 4;

    float acc[4][4];
    #pragma unroll
    for (int i = 0; i < 4; i++)
        #pragma unroll
        for (int j = 0; j < 4; j++) acc[i][j] = 0.f;

    for (int k0 = 0; k0 < LL; k0 += 32) {
        #pragma unroll
        for (int rr = 0; rr < 2; rr++) {
            int r = ar + rr * 32;
            float4 va = *(const float4*)&A[(size_t)(m0 + r) * LL + k0 + ac];
            As[ac + 0][r] = va.x; As[ac + 1][r] = va.y;
            As[ac + 2][r] = va.z; As[ac + 3][r] = va.w;
        }
        #pragma unroll
        for (int rr = 0; rr < 2; rr++) {
            int r = br + rr * 16;
            *(float4*)&Bs[r][bc] = *(const float4*)&V[(size_t)(k0 + r) * DH + bc];
        }
        __syncthreads();
        #pragma unroll
        for (int kk = 0; kk < 32; kk++) {
            float4 a4 = *(const float4*)&As[kk][ty * 4];
            float4 b4 = *(const float4*)&Bs[kk][tx * 4];
            float a[4] = {a4.x, a4.y, a4.z, a4.w};
            float bb[4] = {b4.x, b4.y, b4.z, b4.w};
            #pragma unroll
            for (int i = 0; i < 4; i++)
                #pragma unroll
                for (int j = 0; j < 4; j++)
                    acc[i][j] += a[i] * bb[j];
        }
        __syncthreads();
    }

    int b = bh >> 4, h = bh & 15;
    #pragma unroll
    for (int i = 0; i < 4; i++) {
        int m = m0 + ty * 4 + i;
        float4 o = make_float4(acc[i][0], acc[i][1], acc[i][2], acc[i][3]);
        *(float4*)&g_ctx[((size_t)(b * LL + m)) * DD + h * DH + tx * 4] = o;
        (void)ctx;
    }
}

// ---------------------------------------------------------------------------
extern "C" void kernel_launch(void* const* d_in, const int* in_sizes, int n_in,
                              void* d_out, int out_size)
{
    const float* key   = (const float*)d_in[0];
    const float* value = (const float*)d_in[1];
    const float* query = (const float*)d_in[2];
    const int*   mat   = (const int*)d_in[3];
    const unsigned char* mask = (const unsigned char*)d_in[4];
    const float* Wq = (const float*)d_in[5];
    const float* bq = (const float*)d_in[6];
    const float* Wk = (const float*)d_in[7];
    const float* bk = (const float*)d_in[8];
    const float* Wv = (const float*)d_in[9];
    const float* bv = (const float*)d_in[10];
    const float* Wo = (const float*)d_in[11];
    const float* bo = (const float*)d_in[12];
    const float* semb = (const float*)d_in[13];
    const float* vemb = (const float*)d_in[14];

    float* out  = (float*)d_out;
    float* attn = out + OUT_ELEMS;   // scores buffer, softmaxed in place

    float *q, *k, *v, *ctx;
    cudaGetSymbolAddress((void**)&q,   g_q);
    cudaGetSymbolAddress((void**)&k,   g_k);
    cudaGetSymbolAddress((void**)&v,   g_v);
    cudaGetSymbolAddress((void**)&ctx, g_ctx);

    dim3 gproj(8, 16);
    sgemm_proj<<<gproj, 256>>>(query, Wq, bq, q, 0.125f, 1);
    sgemm_proj<<<gproj, 256>>>(key,   Wk, bk, k, 1.0f,   1);
    sgemm_proj<<<gproj, 256>>>(value, Wv, bv, v, 1.0f,   1);

    qk_kernel<<<dim3(4, 4, BH), 256>>>(attn);
    ast_kernel<<<dim3(LL, BB), 128>>>(mat, semb, vemb, attn);
    softmax_kernel<<<BH * LL, 128>>>(attn, mask);
    av_kernel<<<dim3(8, BH), 256>>>(attn, ctx);

    sgemm_proj<<<gproj, 256>>>(ctx, Wo, bo, out, 1.0f, 0);
}

// round 3
// speedup vs baseline: 2.4153x; 2.4153x over previous
#include <cuda_runtime.h>

// Problem constants
#define BB 4
#define LL 512
#define DD 1024
#define HH 16
#define DH 64
#define BH (BB*HH)            // 64
#define OUT_ELEMS (BB*LL*DD)  // 2097152

// Scratch (no allocations allowed -> __device__ globals)
__device__ float g_q[BB*HH*LL*DH];    // [b][h][l][dh]
__device__ float g_k[BB*HH*LL*DH];    // [b][h][dh][l]  (transposed for qk)
__device__ float g_v[BB*HH*LL*DH];    // [b][h][l][dh]
__device__ float g_ctx[BB*LL*DD];

// ---------------------------------------------------------------------------
// tf32 helpers (mma.sync m16n8k8, row.col, f32 accum)
// ---------------------------------------------------------------------------
__device__ __forceinline__ unsigned f2tf(float x) {
    unsigned y; asm("cvt.rna.tf32.f32 %0, %1;" : "=r"(y) : "f"(x)); return y;
}
__device__ __forceinline__ uint4 cvt4(float4 v) {
    uint4 u; u.x = f2tf(v.x); u.y = f2tf(v.y); u.z = f2tf(v.z); u.w = f2tf(v.w);
    return u;
}
__device__ __forceinline__ void mma8(float* d, const unsigned* a,
                                     const unsigned* b, const float* c) {
    asm volatile(
        "mma.sync.aligned.m16n8k8.row.col.f32.tf32.tf32.f32 "
        "{%0,%1,%2,%3}, {%4,%5,%6,%7}, {%8,%9}, {%10,%11,%12,%13};"
        : "=f"(d[0]), "=f"(d[1]), "=f"(d[2]), "=f"(d[3])
        : "r"(a[0]), "r"(a[1]), "r"(a[2]), "r"(a[3]),
          "r"(b[0]), "r"(b[1]),
          "f"(c[0]), "f"(c[1]), "f"(c[2]), "f"(c[3]));
}

// ---------------------------------------------------------------------------
// K1/K6: C = A(2048x1024) @ W(1024x1024) + bias, scale.
// mode 0: out[m][n]; mode 1: [b][h][l][dh]; mode 2: [b][h][dh][l] (K transp).
// Tile 128x128, BK=32, 256 threads = 8 warps (2m x 4n), warp tile 64x32.
// ---------------------------------------------------------------------------
__global__ __launch_bounds__(256) void proj_tf32(
    const float* __restrict__ A, const float* __restrict__ W,
    const float* __restrict__ bias, float* __restrict__ out,
    float scale, int mode)
{
    __shared__ __align__(16) unsigned As[128 * 36];   // [m][k], pad 36
    __shared__ __align__(16) unsigned Bs[32 * 136];   // [k][n], pad 136
    const int K = 1024, N = 1024;

    int t = threadIdx.x;
    int m0 = blockIdx.y * 128, n0 = blockIdx.x * 128;
    int wid = t >> 5, lane = t & 31;
    int wm = (wid >> 2) * 64, wn = (wid & 3) * 32;
    int g = lane >> 2, tg = lane & 3;

    float acc[4][4][4];
    #pragma unroll
    for (int i = 0; i < 4; i++)
        #pragma unroll
        for (int j = 0; j < 4; j++)
            #pragma unroll
            for (int e = 0; e < 4; e++) acc[i][j][e] = 0.f;

    int a_r = t >> 3, a_c = (t & 7) * 4;
    int b_r = t >> 5, b_c = (t & 31) * 4;

    for (int k0 = 0; k0 < K; k0 += 32) {
        #pragma unroll
        for (int rr = 0; rr < 4; rr++) {
            int r = a_r + rr * 32;
            float4 v = *(const float4*)&A[(m0 + r) * K + k0 + a_c];
            *(uint4*)&As[r * 36 + a_c] = cvt4(v);
        }
        #pragma unroll
        for (int rr = 0; rr < 4; rr++) {
            int r = b_r + rr * 8;
            float4 v = *(const float4*)&W[(k0 + r) * N + n0 + b_c];
            *(uint4*)&Bs[r * 136 + b_c] = cvt4(v);
        }
        __syncthreads();

        #pragma unroll
        for (int kk = 0; kk < 32; kk += 8) {
            unsigned af[4][4], bf[4][2];
            #pragma unroll
            for (int mf = 0; mf < 4; mf++) {
                int row = wm + mf * 16 + g;
                af[mf][0] = As[row * 36 + kk + tg];
                af[mf][1] = As[(row + 8) * 36 + kk + tg];
                af[mf][2] = As[row * 36 + kk + 4 + tg];
                af[mf][3] = As[(row + 8) * 36 + kk + 4 + tg];
            }
            #pragma unroll
            for (int nf = 0; nf < 4; nf++) {
                int col = wn + nf * 8 + g;
                bf[nf][0] = Bs[(kk + tg) * 136 + col];
                bf[nf][1] = Bs[(kk + 4 + tg) * 136 + col];
            }
            #pragma unroll
            for (int mf = 0; mf < 4; mf++)
                #pragma unroll
                for (int nf = 0; nf < 4; nf++)
                    mma8(acc[mf][nf], af[mf], bf[nf], acc[mf][nf]);
        }
        __syncthreads();
    }

    #pragma unroll
    for (int mf = 0; mf < 4; mf++) {
        #pragma unroll
        for (int nf = 0; nf < 4; nf++) {
            int col = n0 + wn + nf * 8 + 2 * tg;
            float2 b2 = *(const float2*)&bias[col];
            #pragma unroll
            for (int rr = 0; rr < 2; rr++) {
                int m = m0 + wm + mf * 16 + g + rr * 8;
                float vx = (acc[mf][nf][rr * 2 + 0] + b2.x) * scale;
                float vy = (acc[mf][nf][rr * 2 + 1] + b2.y) * scale;
                if (mode == 0) {
                    *(float2*)&out[m * 1024 + col] = make_float2(vx, vy);
                } else {
                    int b = m >> 9, l = m & 511;
                    int h = col >> 6, dh = col & 63;
                    if (mode == 1) {
                        *(float2*)&out[((b * HH + h) * LL + l) * DH + dh] =
                            make_float2(vx, vy);
                    } else {
                        out[((b * HH + h) * DH + dh) * LL + l] = vx;
                        out[((b * HH + h) * DH + dh + 1) * LL + l] = vy;
                    }
                }
            }
        }
    }
}

// ---------------------------------------------------------------------------
// K2: scores[bh][i][j] = q[bh][i][:] . kT[bh][:][j]   (M=N=512, K=64 per bh)
// kT is [dh][l] so B tile is a direct copy. Tile 128x128, BK=32.
// ---------------------------------------------------------------------------
__global__ __launch_bounds__(256) void qk_tf32(float* __restrict__ scores)
{
    __shared__ __align__(16) unsigned As[128 * 36];
    __shared__ __align__(16) unsigned Bs[32 * 136];

    int t = threadIdx.x;
    int bh = blockIdx.z;
    const float* Q  = g_q + bh * LL * DH;   // [l][dh]
    const float* KT = g_k + bh * LL * DH;   // [dh][l]
    int m0 = blockIdx.y * 128, n0 = blockIdx.x * 128;
    int wid = t >> 5, lane = t & 31;
    int wm = (wid >> 2) * 64, wn = (wid & 3) * 32;
    int g = lane >> 2, tg = lane & 3;

    float acc[4][4][4];
    #pragma unroll
    for (int i = 0; i < 4; i++)
        #pragma unroll
        for (int j = 0; j < 4; j++)
            #pragma unroll
            for (int e = 0; e < 4; e++) acc[i][j][e] = 0.f;

    int a_r = t >> 3, a_c = (t & 7) * 4;
    int b_r = t >> 5, b_c = (t & 31) * 4;

    for (int k0 = 0; k0 < DH; k0 += 32) {
        #pragma unroll
        for (int rr = 0; rr < 4; rr++) {
            int r = a_r + rr * 32;
            float4 v = *(const float4*)&Q[(m0 + r) * DH + k0 + a_c];
            *(uint4*)&As[r * 36 + a_c] = cvt4(v);
        }
        #pragma unroll
        for (int rr = 0; rr < 4; rr++) {
            int r = b_r + rr * 8;
            float4 v = *(const float4*)&KT[(k0 + r) * LL + n0 + b_c];
            *(uint4*)&Bs[r * 136 + b_c] = cvt4(v);
        }
        __syncthreads();

        #pragma unroll
        for (int kk = 0; kk < 32; kk += 8) {
            unsigned af[4][4], bf[4][2];
            #pragma unroll
            for (int mf = 0; mf < 4; mf++) {
                int row = wm + mf * 16 + g;
                af[mf][0] = As[row * 36 + kk + tg];
                af[mf][1] = As[(row + 8) * 36 + kk + tg];
                af[mf][2] = As[row * 36 + kk + 4 + tg];
                af[mf][3] = As[(row + 8) * 36 + kk + 4 + tg];
            }
            #pragma unroll
            for (int nf = 0; nf < 4; nf++) {
                int col = wn + nf * 8 + g;
                bf[nf][0] = Bs[(kk + tg) * 136 + col];
                bf[nf][1] = Bs[(kk + 4 + tg) * 136 + col];
            }
            #pragma unroll
            for (int mf = 0; mf < 4; mf++)
                #pragma unroll
                for (int nf = 0; nf < 4; nf++)
                    mma8(acc[mf][nf], af[mf], bf[nf], acc[mf][nf]);
        }
        __syncthreads();
    }

    float* srow = scores + (size_t)bh * LL * LL;
    #pragma unroll
    for (int mf = 0; mf < 4; mf++)
        #pragma unroll
        for (int nf = 0; nf < 4; nf++) {
            int col = n0 + wn + nf * 8 + 2 * tg;
            #pragma unroll
            for (int rr = 0; rr < 2; rr++) {
                int m = m0 + wm + mf * 16 + g + rr * 8;
                *(float2*)&srow[m * LL + col] =
                    make_float2(acc[mf][nf][rr * 2], acc[mf][nf][rr * 2 + 1]);
            }
        }
}

// ---------------------------------------------------------------------------
// K3: scores[b][h][i][j] += q[b][h][i][:] . emb(mat[b][i][j])[:]
// Per (i,b): A = q heads (16x64), B = gathered pe (j x 64). tf32 MMA, M=16.
// 128 threads = 4 warps, each warp takes 32 j per 128-j tile. A-frags hoisted.
// ---------------------------------------------------------------------------
__global__ __launch_bounds__(128) void ast_tf32(
    const int* __restrict__ mat, const float* __restrict__ semb,
    const float* __restrict__ vemb, float* __restrict__ scores)
{
    __shared__ __align__(16) unsigned qs[16 * 68];   // [h][d], pad 68
    __shared__ __align__(16) unsigned pe[128 * 68];  // [j][d], pad 68

    int i = blockIdx.x, b = blockIdx.y;
    int t = threadIdx.x;
    int wid = t >> 5, lane = t & 31;
    int g = lane >> 2, tg = lane & 3;

    for (int idx = t; idx < HH * DH; idx += 128) {
        int h = idx >> 6, d = idx & 63;
        qs[h * 68 + d] = f2tf(g_q[((b * HH + h) * LL + i) * DH + d]);
    }
    __syncthreads();

    // Hoist A fragments (constant over j): 8 k-steps x 4 regs
    unsigned af[8][4];
    #pragma unroll
    for (int ks = 0; ks < 8; ks++) {
        af[ks][0] = qs[g * 68 + ks * 8 + tg];
        af[ks][1] = qs[(g + 8) * 68 + ks * 8 + tg];
        af[ks][2] = qs[g * 68 + ks * 8 + 4 + tg];
        af[ks][3] = qs[(g + 8) * 68 + ks * 8 + 4 + tg];
    }

    const int* mrow = mat + (b * LL + i) * LL;

    for (int jt = 0; jt < 4; jt++) {
        int j0 = jt * 128;
        __syncthreads();   // protect pe reuse across jt
        {
            int j = j0 + t;
            int id = mrow[j];
            const float* e = ((j & 1) ? vemb : semb) + id * DH;
            #pragma unroll
            for (int s = 0; s < 64; s += 4)
                *(uint4*)&pe[t * 68 + s] = cvt4(*(const float4*)&e[s]);
        }
        __syncthreads();

        float acc[4][4];
        #pragma unroll
        for (int nf = 0; nf < 4; nf++)
            #pragma unroll
            for (int e = 0; e < 4; e++) acc[nf][e] = 0.f;

        #pragma unroll
        for (int ks = 0; ks < 8; ks++) {
            #pragma unroll
            for (int nf = 0; nf < 4; nf++) {
                int jj = wid * 32 + nf * 8 + g;
                unsigned bf[2];
                bf[0] = pe[jj * 68 + ks * 8 + tg];
                bf[1] = pe[jj * 68 + ks * 8 + 4 + tg];
                mma8(acc[nf], af[ks], bf, acc[nf]);
            }
        }

        #pragma unroll
        for (int nf = 0; nf < 4; nf++) {
            int col = j0 + wid * 32 + nf * 8 + 2 * tg;
            float2* p0 = (float2*)&scores[(((size_t)(b * HH + g) * LL + i) * LL) + col];
            float2 v0 = *p0; v0.x += acc[nf][0]; v0.y += acc[nf][1]; *p0 = v0;
            float2* p1 = (float2*)&scores[(((size_t)(b * HH + g + 8) * LL + i) * LL) + col];
            float2 v1 = *p1; v1.x += acc[nf][2]; v1.y += acc[nf][3]; *p1 = v1;
        }
    }
}

// ---------------------------------------------------------------------------
// K4: in-place masked softmax over last dim (512). One block (128 thr) per row.
// ---------------------------------------------------------------------------
__global__ __launch_bounds__(128) void softmax_kernel(
    float* __restrict__ attn, const unsigned char* __restrict__ mask)
{
    int row = blockIdx.x;              // (b*H + h)*L + i
    int b   = row >> 13;
    int t   = threadIdx.x;
    size_t base = (size_t)row * LL + t * 4;

    float4 s = *(float4*)&attn[base];
    const unsigned char* mk = mask + b * LL + t * 4;
    if (mk[0]) s.x = -1e18f;
    if (mk[1]) s.y = -1e18f;
    if (mk[2]) s.z = -1e18f;
    if (mk[3]) s.w = -1e18f;

    float mx = fmaxf(fmaxf(s.x, s.y), fmaxf(s.z, s.w));
    #pragma unroll
    for (int o = 16; o > 0; o >>= 1)
        mx = fmaxf(mx, __shfl_xor_sync(0xffffffffu, mx, o));

    __shared__ float red[8];
    int w = t >> 5, ln = t & 31;
    if (ln == 0) red[w] = mx;
    __syncthreads();
    mx = fmaxf(fmaxf(red[0], red[1]), fmaxf(red[2], red[3]));

    float e0 = __expf(s.x - mx);
    float e1 = __expf(s.y - mx);
    float e2 = __expf(s.z - mx);
    float e3 = __expf(s.w - mx);
    float sm = e0 + e1 + e2 + e3;
    #pragma unroll
    for (int o = 16; o > 0; o >>= 1)
        sm += __shfl_xor_sync(0xffffffffu, sm, o);
    if (ln == 0) red[4 + w] = sm;
    __syncthreads();
    sm = red[4] + red[5] + red[6] + red[7];

    float inv = 1.0f / sm;
    s.x = e0 * inv; s.y = e1 * inv; s.z = e2 * inv; s.w = e3 * inv;
    *(float4*)&attn[base] = s;
}

// ---------------------------------------------------------------------------
// K5: ctx[b][i][h*64+d] = sum_j attn[bh][i][j] * v[bh][j][d]
// Per bh: M=512 N=64 K=512. Tile 128x64, BK=32, 8 warps (4m x 2n), warp 32x32.
// ---------------------------------------------------------------------------
__global__ __launch_bounds__(256) void av_tf32(const float* __restrict__ attn)
{
    __shared__ __align__(16) unsigned As[128 * 36];  // [m][k] pad 36
    __shared__ __align__(16) unsigned Bs[32 * 72];   // [k][n] pad 72

    int t = threadIdx.x;
    int bh = blockIdx.y;
    int m0 = blockIdx.x * 128;
    const float* A = attn + (size_t)bh * LL * LL;
    const float* V = g_v + bh * LL * DH;
    int wid = t >> 5, lane = t & 31;
    int wm = (wid >> 1) * 32, wn = (wid & 1) * 32;
    int g = lane >> 2, tg = lane & 3;

    float acc[2][4][4];
    #pragma unroll
    for (int i = 0; i < 2; i++)
        #pragma unroll
        for (int j = 0; j < 4; j++)
            #pragma unroll
            for (int e = 0; e < 4; e++) acc[i][j][e] = 0.f;

    int a_r = t >> 3, a_c = (t & 7) * 4;
    int b_r = t >> 4, b_c = (t & 15) * 4;

    for (int k0 = 0; k0 < LL; k0 += 32) {
        #pragma unroll
        for (int rr = 0; rr < 4; rr++) {
            int r = a_r + rr * 32;
            float4 v = *(const float4*)&A[(size_t)(m0 + r) * LL + k0 + a_c];
            *(uint4*)&As[r * 36 + a_c] = cvt4(v);
        }
        #pragma unroll
        for (int rr = 0; rr < 2; rr++) {
            int r = b_r + rr * 16;
            float4 v = *(const float4*)&V[(k0 + r) * DH + b_c];
            *(uint4*)&Bs[r * 72 + b_c] = cvt4(v);
        }
        __syncthreads();

        #pragma unroll
        for (int kk = 0; kk < 32; kk += 8) {
            unsigned af[2][4], bf[4][2];
            #pragma unroll
            for (int mf = 0; mf < 2; mf++) {
                int row = wm + mf * 16 + g;
                af[mf][0] = As[row * 36 + kk + tg];
                af[mf][1] = As[(row + 8) * 36 + kk + tg];
                af[mf][2] = As[row * 36 + kk + 4 + tg];
                af[mf][3] = As[(row + 8) * 36 + kk + 4 + tg];
            }
            #pragma unroll
            for (int nf = 0; nf < 4; nf++) {
                int col = wn + nf * 8 + g;
                bf[nf][0] = Bs[(kk + tg) * 72 + col];
                bf[nf][1] = Bs[(kk + 4 + tg) * 72 + col];
            }
            #pragma unroll
            for (int mf = 0; mf < 2; mf++)
                #pragma unroll
                for (int nf = 0; nf < 4; nf++)
                    mma8(acc[mf][nf], af[mf], bf[nf], acc[mf][nf]);
        }
        __syncthreads();
    }

    int b = bh >> 4, h = bh & 15;
    #pragma unroll
    for (int mf = 0; mf < 2; mf++)
        #pragma unroll
        for (int nf = 0; nf < 4; nf++) {
            int n = wn + nf * 8 + 2 * tg;
            #pragma unroll
            for (int rr = 0; rr < 2; rr++) {
                int l = m0 + wm + mf * 16 + g + rr * 8;
                *(float2*)&g_ctx[((b * LL + l) * DD) + h * DH + n] =
                    make_float2(acc[mf][nf][rr * 2], acc[mf][nf][rr * 2 + 1]);
            }
        }
}

// ---------------------------------------------------------------------------
extern "C" void kernel_launch(void* const* d_in, const int* in_sizes, int n_in,
                              void* d_out, int out_size)
{
    const float* key   = (const float*)d_in[0];
    const float* value = (const float*)d_in[1];
    const float* query = (const float*)d_in[2];
    const int*   mat   = (const int*)d_in[3];
    const unsigned char* mask = (const unsigned char*)d_in[4];
    const float* Wq = (const float*)d_in[5];
    const float* bq = (const float*)d_in[6];
    const float* Wk = (const float*)d_in[7];
    const float* bk = (const float*)d_in[8];
    const float* Wv = (const float*)d_in[9];
    const float* bv = (const float*)d_in[10];
    const float* Wo = (const float*)d_in[11];
    const float* bo = (const float*)d_in[12];
    const float* semb = (const float*)d_in[13];
    const float* vemb = (const float*)d_in[14];

    float* out  = (float*)d_out;
    float* attn = out + OUT_ELEMS;   // scores buffer, softmaxed in place

    float *q, *k, *v, *ctx;
    cudaGetSymbolAddress((void**)&q,   g_q);
    cudaGetSymbolAddress((void**)&k,   g_k);
    cudaGetSymbolAddress((void**)&v,   g_v);
    cudaGetSymbolAddress((void**)&ctx, g_ctx);

    dim3 gproj(8, 16);
    proj_tf32<<<gproj, 256>>>(query, Wq, bq, q, 0.125f, 1);
    proj_tf32<<<gproj, 256>>>(key,   Wk, bk, k, 1.0f,   2);   // transposed K
    proj_tf32<<<gproj, 256>>>(value, Wv, bv, v, 1.0f,   1);

    qk_tf32<<<dim3(4, 4, BH), 256>>>(attn);
    ast_tf32<<<dim3(LL, BB), 128>>>(mat, semb, vemb, attn);
    softmax_kernel<<<BH * LL, 128>>>(attn, mask);
    av_tf32<<<dim3(4, BH), 256>>>(attn);

    proj_tf32<<<gproj, 256>>>(ctx, Wo, bo, out, 1.0f, 0);
}

// round 5
// speedup vs baseline: 2.7795x; 1.1508x over previous
#include <cuda_runtime.h>

// Problem constants
#define BB 4
#define LL 512
#define DD 1024
#define HH 16
#define DH 64
#define BH (BB*HH)            // 64
#define OUT_ELEMS (BB*LL*DD)  // 2097152

// Scratch (no allocations allowed -> __device__ globals)
__device__ float g_q[BB*HH*LL*DH];    // [b][h][l][dh]
__device__ float g_k[BB*HH*LL*DH];    // [b][h][dh][l]  (transposed for qk)
__device__ float g_v[BB*HH*LL*DH];    // [b][h][l][dh]
__device__ float g_ctx[BB*LL*DD];

// ---------------------------------------------------------------------------
// tf32 helpers (mma.sync m16n8k8, row.col, f32 accum)
// ---------------------------------------------------------------------------
__device__ __forceinline__ unsigned f2tf(float x) {
    unsigned y; asm("cvt.rna.tf32.f32 %0, %1;" : "=r"(y) : "f"(x)); return y;
}
__device__ __forceinline__ uint4 cvt4(float4 v) {
    uint4 u; u.x = f2tf(v.x); u.y = f2tf(v.y); u.z = f2tf(v.z); u.w = f2tf(v.w);
    return u;
}
__device__ __forceinline__ void mma8(float* d, const unsigned* a,
                                     const unsigned* b, const float* c) {
    asm volatile(
        "mma.sync.aligned.m16n8k8.row.col.f32.tf32.tf32.f32 "
        "{%0,%1,%2,%3}, {%4,%5,%6,%7}, {%8,%9}, {%10,%11,%12,%13};"
        : "=f"(d[0]), "=f"(d[1]), "=f"(d[2]), "=f"(d[3])
        : "r"(a[0]), "r"(a[1]), "r"(a[2]), "r"(a[3]),
          "r"(b[0]), "r"(b[1]),
          "f"(c[0]), "f"(c[1]), "f"(c[2]), "f"(c[3]));
}

// Smem strides chosen conflict-free:
//   As stride 20  (20 mod 32 = 4  -> frag banks 4g+tg = lane, all distinct)
//   Bs stride 136 (136 mod 32 = 8 -> frag banks 8tg+g, all distinct, g<8)
//   Bs64 stride 72 (72 mod 32 = 8)
#define AS_S 20
#define BS_S 136
#define BS64_S 72

struct PArg { const float* A; const float* W; const float* bias;
              float* out; float scale; int mode; };
struct PArgs { PArg p[3]; };

// ---------------------------------------------------------------------------
// Projection GEMM: C = A(2048x1024) @ W(1024x1024) + bias, scale.
// mode 0: out[m][n]; mode 1: [b][h][l][dh]; mode 2: [b][h][dh][l].
// Tile 128x128, BK=16, 2-stage smem double buffer + register prefetch.
// 8 warps (2m x 4n), warp tile 64x32. blockIdx.z selects the projection.
// ---------------------------------------------------------------------------
__global__ __launch_bounds__(256, 2) void proj_tf32(PArgs args)
{
    __shared__ __align__(16) unsigned As[2][128 * AS_S];
    __shared__ __align__(16) unsigned Bs[2][16 * BS_S];
    const int K = 1024, N = 1024;

    PArg pa = args.p[blockIdx.z];
    const float* __restrict__ A = pa.A;
    const float* __restrict__ W = pa.W;

    int t = threadIdx.x;
    int m0 = blockIdx.y * 128, n0 = blockIdx.x * 128;
    int wid = t >> 5, lane = t & 31;
    int wm = (wid >> 2) * 64, wn = (wid & 3) * 32;
    int g = lane >> 2, tg = lane & 3;

    // loader indices: A tile 128x16 (2 float4/thr), B tile 16x128 (2 float4/thr)
    int a_r = t >> 2;            // 0..63 (+64)
    int a_c = (t & 3) * 4;
    int b_r = t >> 5;            // 0..7 (+8)
    int b_c = (t & 31) * 4;

    float acc[4][4][4];
    #pragma unroll
    for (int i = 0; i < 4; i++)
        #pragma unroll
        for (int j = 0; j < 4; j++)
            #pragma unroll
            for (int e = 0; e < 4; e++) acc[i][j][e] = 0.f;

    float4 ra0, ra1, rb0, rb1;
    ra0 = *(const float4*)&A[(m0 + a_r) * K + a_c];
    ra1 = *(const float4*)&A[(m0 + a_r + 64) * K + a_c];
    rb0 = *(const float4*)&W[b_r * N + n0 + b_c];
    rb1 = *(const float4*)&W[(b_r + 8) * N + n0 + b_c];

    int p = 0;
    *(uint4*)&As[0][a_r * AS_S + a_c]        = cvt4(ra0);
    *(uint4*)&As[0][(a_r + 64) * AS_S + a_c] = cvt4(ra1);
    *(uint4*)&Bs[0][b_r * BS_S + b_c]        = cvt4(rb0);
    *(uint4*)&Bs[0][(b_r + 8) * BS_S + b_c]  = cvt4(rb1);
    __syncthreads();

    for (int k0 = 16; k0 < K; k0 += 16) {
        ra0 = *(const float4*)&A[(m0 + a_r) * K + k0 + a_c];
        ra1 = *(const float4*)&A[(m0 + a_r + 64) * K + k0 + a_c];
        rb0 = *(const float4*)&W[(k0 + b_r) * N + n0 + b_c];
        rb1 = *(const float4*)&W[(k0 + b_r + 8) * N + n0 + b_c];

        #pragma unroll
        for (int kk = 0; kk < 16; kk += 8) {
            unsigned af[4][4], bf[4][2];
            #pragma unroll
            for (int mf = 0; mf < 4; mf++) {
                int row = wm + mf * 16 + g;
                af[mf][0] = As[p][row * AS_S + kk + tg];
                af[mf][1] = As[p][(row + 8) * AS_S + kk + tg];
                af[mf][2] = As[p][row * AS_S + kk + 4 + tg];
                af[mf][3] = As[p][(row + 8) * AS_S + kk + 4 + tg];
            }
            #pragma unroll
            for (int nf = 0; nf < 4; nf++) {
                int col = wn + nf * 8 + g;
                bf[nf][0] = Bs[p][(kk + tg) * BS_S + col];
                bf[nf][1] = Bs[p][(kk + 4 + tg) * BS_S + col];
            }
            #pragma unroll
            for (int mf = 0; mf < 4; mf++)
                #pragma unroll
                for (int nf = 0; nf < 4; nf++)
                    mma8(acc[mf][nf], af[mf], bf[nf], acc[mf][nf]);
        }

        int q = p ^ 1;
        *(uint4*)&As[q][a_r * AS_S + a_c]        = cvt4(ra0);
        *(uint4*)&As[q][(a_r + 64) * AS_S + a_c] = cvt4(ra1);
        *(uint4*)&Bs[q][b_r * BS_S + b_c]        = cvt4(rb0);
        *(uint4*)&Bs[q][(b_r + 8) * BS_S + b_c]  = cvt4(rb1);
        __syncthreads();
        p = q;
    }

    // last tile
    #pragma unroll
    for (int kk = 0; kk < 16; kk += 8) {
        unsigned af[4][4], bf[4][2];
        #pragma unroll
        for (int mf = 0; mf < 4; mf++) {
            int row = wm + mf * 16 + g;
            af[mf][0] = As[p][row * AS_S + kk + tg];
            af[mf][1] = As[p][(row + 8) * AS_S + kk + tg];
            af[mf][2] = As[p][row * AS_S + kk + 4 + tg];
            af[mf][3] = As[p][(row + 8) * AS_S + kk + 4 + tg];
        }
        #pragma unroll
        for (int nf = 0; nf < 4; nf++) {
            int col = wn + nf * 8 + g;
            bf[nf][0] = Bs[p][(kk + tg) * BS_S + col];
            bf[nf][1] = Bs[p][(kk + 4 + tg) * BS_S + col];
        }
        #pragma unroll
        for (int mf = 0; mf < 4; mf++)
            #pragma unroll
            for (int nf = 0; nf < 4; nf++)
                mma8(acc[mf][nf], af[mf], bf[nf], acc[mf][nf]);
    }

    #pragma unroll
    for (int mf = 0; mf < 4; mf++) {
        #pragma unroll
        for (int nf = 0; nf < 4; nf++) {
            int col = n0 + wn + nf * 8 + 2 * tg;
            float2 b2 = *(const float2*)&pa.bias[col];
            #pragma unroll
            for (int rr = 0; rr < 2; rr++) {
                int m = m0 + wm + mf * 16 + g + rr * 8;
                float vx = (acc[mf][nf][rr * 2 + 0] + b2.x) * pa.scale;
                float vy = (acc[mf][nf][rr * 2 + 1] + b2.y) * pa.scale;
                if (pa.mode == 0) {
                    *(float2*)&pa.out[m * 1024 + col] = make_float2(vx, vy);
                } else {
                    int b = m >> 9, l = m & 511;
                    int h = col >> 6, dh = col & 63;
                    if (pa.mode == 1) {
                        *(float2*)&pa.out[((b * HH + h) * LL + l) * DH + dh] =
                            make_float2(vx, vy);
                    } else {
                        pa.out[((b * HH + h) * DH + dh) * LL + l] = vx;
                        pa.out[((b * HH + h) * DH + dh + 1) * LL + l] = vy;
                    }
                }
            }
        }
    }
}

// ---------------------------------------------------------------------------
// qk: scores[bh][i][j] = q[bh][i][:] . kT[bh][:][j]  (M=N=512, K=64 per bh)
// Same pipelined structure, 4 K-iterations.
// ---------------------------------------------------------------------------
__global__ __launch_bounds__(256, 2) void qk_tf32(float* __restrict__ scores)
{
    __shared__ __align__(16) unsigned As[2][128 * AS_S];
    __shared__ __align__(16) unsigned Bs[2][16 * BS_S];

    int t = threadIdx.x;
    int bh = blockIdx.z;
    const float* __restrict__ Q  = g_q + bh * LL * DH;   // [l][dh], stride 64
    const float* __restrict__ KT = g_k + bh * LL * DH;   // [dh][l], stride 512
    int m0 = blockIdx.y * 128, n0 = blockIdx.x * 128;
    int wid = t >> 5, lane = t & 31;
    int wm = (wid >> 2) * 64, wn = (wid & 3) * 32;
    int g = lane >> 2, tg = lane & 3;

    int a_r = t >> 2, a_c = (t & 3) * 4;
    int b_r = t >> 5, b_c = (t & 31) * 4;

    float acc[4][4][4];
    #pragma unroll
    for (int i = 0; i < 4; i++)
        #pragma unroll
        for (int j = 0; j < 4; j++)
            #pragma unroll
            for (int e = 0; e < 4; e++) acc[i][j][e] = 0.f;

    float4 ra0, ra1, rb0, rb1;
    ra0 = *(const float4*)&Q[(m0 + a_r) * DH + a_c];
    ra1 = *(const float4*)&Q[(m0 + a_r + 64) * DH + a_c];
    rb0 = *(const float4*)&KT[b_r * LL + n0 + b_c];
    rb1 = *(const float4*)&KT[(b_r + 8) * LL + n0 + b_c];

    int p = 0;
    *(uint4*)&As[0][a_r * AS_S + a_c]        = cvt4(ra0);
    *(uint4*)&As[0][(a_r + 64) * AS_S + a_c] = cvt4(ra1);
    *(uint4*)&Bs[0][b_r * BS_S + b_c]        = cvt4(rb0);
    *(uint4*)&Bs[0][(b_r + 8) * BS_S + b_c]  = cvt4(rb1);
    __syncthreads();

    for (int k0 = 16; k0 < DH; k0 += 16) {
        ra0 = *(const float4*)&Q[(m0 + a_r) * DH + k0 + a_c];
        ra1 = *(const float4*)&Q[(m0 + a_r + 64) * DH + k0 + a_c];
        rb0 = *(const float4*)&KT[(k0 + b_r) * LL + n0 + b_c];
        rb1 = *(const float4*)&KT[(k0 + b_r + 8) * LL + n0 + b_c];

        #pragma unroll
        for (int kk = 0; kk < 16; kk += 8) {
            unsigned af[4][4], bf[4][2];
            #pragma unroll
            for (int mf = 0; mf < 4; mf++) {
                int row = wm + mf * 16 + g;
                af[mf][0] = As[p][row * AS_S + kk + tg];
                af[mf][1] = As[p][(row + 8) * AS_S + kk + tg];
                af[mf][2] = As[p][row * AS_S + kk + 4 + tg];
                af[mf][3] = As[p][(row + 8) * AS_S + kk + 4 + tg];
            }
            #pragma unroll
            for (int nf = 0; nf < 4; nf++) {
                int col = wn + nf * 8 + g;
                bf[nf][0] = Bs[p][(kk + tg) * BS_S + col];
                bf[nf][1] = Bs[p][(kk + 4 + tg) * BS_S + col];
            }
            #pragma unroll
            for (int mf = 0; mf < 4; mf++)
                #pragma unroll
                for (int nf = 0; nf < 4; nf++)
                    mma8(acc[mf][nf], af[mf], bf[nf], acc[mf][nf]);
        }

        int q = p ^ 1;
        *(uint4*)&As[q][a_r * AS_S + a_c]        = cvt4(ra0);
        *(uint4*)&As[q][(a_r + 64) * AS_S + a_c] = cvt4(ra1);
        *(uint4*)&Bs[q][b_r * BS_S + b_c]        = cvt4(rb0);
        *(uint4*)&Bs[q][(b_r + 8) * BS_S + b_c]  = cvt4(rb1);
        __syncthreads();
        p = q;
    }

    #pragma unroll
    for (int kk = 0; kk < 16; kk += 8) {
        unsigned af[4][4], bf[4][2];
        #pragma unroll
        for (int mf = 0; mf < 4; mf++) {
            int row = wm + mf * 16 + g;
            af[mf][0] = As[p][row * AS_S + kk + tg];
            af[mf][1] = As[p][(row + 8) * AS_S + kk + tg];
            af[mf][2] = As[p][row * AS_S + kk + 4 + tg];
            af[mf][3] = As[p][(row + 8) * AS_S + kk + 4 + tg];
        }
        #pragma unroll
        for (int nf = 0; nf < 4; nf++) {
            int col = wn + nf * 8 + g;
            bf[nf][0] = Bs[p][(kk + tg) * BS_S + col];
            bf[nf][1] = Bs[p][(kk + 4 + tg) * BS_S + col];
        }
        #pragma unroll
        for (int mf = 0; mf < 4; mf++)
            #pragma unroll
            for (int nf = 0; nf < 4; nf++)
                mma8(acc[mf][nf], af[mf], bf[nf], acc[mf][nf]);
    }

    float* srow = scores + (size_t)bh * LL * LL;
    #pragma unroll
    for (int mf = 0; mf < 4; mf++)
        #pragma unroll
        for (int nf = 0; nf < 4; nf++) {
            int col = n0 + wn + nf * 8 + 2 * tg;
            #pragma unroll
            for (int rr = 0; rr < 2; rr++) {
                int m = m0 + wm + mf * 16 + g + rr * 8;
                *(float2*)&srow[m * LL + col] =
                    make_float2(acc[mf][nf][rr * 2], acc[mf][nf][rr * 2 + 1]);
            }
        }
}

// ---------------------------------------------------------------------------
// ast: scores[b][h][i][j] += q[b][h][i][:] . emb(mat[b][i][j])[:]
// ---------------------------------------------------------------------------
__global__ __launch_bounds__(128) void ast_tf32(
    const int* __restrict__ mat, const float* __restrict__ semb,
    const float* __restrict__ vemb, float* __restrict__ scores)
{
    __shared__ __align__(16) unsigned qs[16 * 68];
    __shared__ __align__(16) unsigned pe[128 * 68];

    int i = blockIdx.x, b = blockIdx.y;
    int t = threadIdx.x;
    int wid = t >> 5, lane = t & 31;
    int g = lane >> 2, tg = lane & 3;

    for (int idx = t; idx < HH * DH; idx += 128) {
        int h = idx >> 6, d = idx & 63;
        qs[h * 68 + d] = f2tf(g_q[((b * HH + h) * LL + i) * DH + d]);
    }
    __syncthreads();

    unsigned af[8][4];
    #pragma unroll
    for (int ks = 0; ks < 8; ks++) {
        af[ks][0] = qs[g * 68 + ks * 8 + tg];
        af[ks][1] = qs[(g + 8) * 68 + ks * 8 + tg];
        af[ks][2] = qs[g * 68 + ks * 8 + 4 + tg];
        af[ks][3] = qs[(g + 8) * 68 + ks * 8 + 4 + tg];
    }

    const int* mrow = mat + (b * LL + i) * LL;

    for (int jt = 0; jt < 4; jt++) {
        int j0 = jt * 128;
        __syncthreads();
        {
            int j = j0 + t;
            int id = mrow[j];
            const float* e = ((j & 1) ? vemb : semb) + id * DH;
            #pragma unroll
            for (int s = 0; s < 64; s += 4)
                *(uint4*)&pe[t * 68 + s] = cvt4(*(const float4*)&e[s]);
        }
        __syncthreads();

        float acc[4][4];
        #pragma unroll
        for (int nf = 0; nf < 4; nf++)
            #pragma unroll
            for (int e = 0; e < 4; e++) acc[nf][e] = 0.f;

        #pragma unroll
        for (int ks = 0; ks < 8; ks++) {
            #pragma unroll
            for (int nf = 0; nf < 4; nf++) {
                int jj = wid * 32 + nf * 8 + g;
                unsigned bf[2];
                bf[0] = pe[jj * 68 + ks * 8 + tg];
                bf[1] = pe[jj * 68 + ks * 8 + 4 + tg];
                mma8(acc[nf], af[ks], bf, acc[nf]);
            }
        }

        #pragma unroll
        for (int nf = 0; nf < 4; nf++) {
            int col = j0 + wid * 32 + nf * 8 + 2 * tg;
            float2* p0 = (float2*)&scores[(((size_t)(b * HH + g) * LL + i) * LL) + col];
            float2 v0 = *p0; v0.x += acc[nf][0]; v0.y += acc[nf][1]; *p0 = v0;
            float2* p1 = (float2*)&scores[(((size_t)(b * HH + g + 8) * LL + i) * LL) + col];
            float2 v1 = *p1; v1.x += acc[nf][2]; v1.y += acc[nf][3]; *p1 = v1;
        }
    }
}

// ---------------------------------------------------------------------------
// softmax: in-place masked softmax over last dim (512). 128 thr per row.
// ---------------------------------------------------------------------------
__global__ __launch_bounds__(128) void softmax_kernel(
    float* __restrict__ attn, const unsigned char* __restrict__ mask)
{
    int row = blockIdx.x;
    int b   = row >> 13;
    int t   = threadIdx.x;
    size_t base = (size_t)row * LL + t * 4;

    float4 s = *(float4*)&attn[base];
    const unsigned char* mk = mask + b * LL + t * 4;
    if (mk[0]) s.x = -1e18f;
    if (mk[1]) s.y = -1e18f;
    if (mk[2]) s.z = -1e18f;
    if (mk[3]) s.w = -1e18f;

    float mx = fmaxf(fmaxf(s.x, s.y), fmaxf(s.z, s.w));
    #pragma unroll
    for (int o = 16; o > 0; o >>= 1)
        mx = fmaxf(mx, __shfl_xor_sync(0xffffffffu, mx, o));

    __shared__ float red[8];
    int w = t >> 5, ln = t & 31;
    if (ln == 0) red[w] = mx;
    __syncthreads();
    mx = fmaxf(fmaxf(red[0], red[1]), fmaxf(red[2], red[3]));

    float e0 = __expf(s.x - mx);
    float e1 = __expf(s.y - mx);
    float e2 = __expf(s.z - mx);
    float e3 = __expf(s.w - mx);
    float sm = e0 + e1 + e2 + e3;
    #pragma unroll
    for (int o = 16; o > 0; o >>= 1)
        sm += __shfl_xor_sync(0xffffffffu, sm, o);
    if (ln == 0) red[4 + w] = sm;
    __syncthreads();
    sm = red[4] + red[5] + red[6] + red[7];

    float inv = 1.0f / sm;
    s.x = e0 * inv; s.y = e1 * inv; s.z = e2 * inv; s.w = e3 * inv;
    *(float4*)&attn[base] = s;
}

// ---------------------------------------------------------------------------
// av: ctx[b][l][h*64+d] = sum_j attn[bh][l][j] * v[bh][j][d]
// Per bh: M=512 N=64 K=512. Tile 128x64, BK=16, 2-stage pipeline.
// 8 warps (4m x 2n), warp tile 32x32.
// ---------------------------------------------------------------------------
__global__ __launch_bounds__(256, 2) void av_tf32(const float* __restrict__ attn)
{
    __shared__ __align__(16) unsigned As[2][128 * AS_S];
    __shared__ __align__(16) unsigned Bs[2][16 * BS64_S];

    int t = threadIdx.x;
    int bh = blockIdx.y;
    int m0 = blockIdx.x * 128;
    const float* __restrict__ A = attn + (size_t)bh * LL * LL;
    const float* __restrict__ V = g_v + bh * LL * DH;
    int wid = t >> 5, lane = t & 31;
    int wm = (wid >> 1) * 32, wn = (wid & 1) * 32;
    int g = lane >> 2, tg = lane & 3;

    int a_r = t >> 2, a_c = (t & 3) * 4;   // A tile 128x16
    int b_r = t >> 4, b_c = (t & 15) * 4;  // B tile 16x64, 1 float4/thr

    float acc[2][4][4];
    #pragma unroll
    for (int i = 0; i < 2; i++)
        #pragma unroll
        for (int j = 0; j < 4; j++)
            #pragma unroll
            for (int e = 0; e < 4; e++) acc[i][j][e] = 0.f;

    float4 ra0, ra1, rb0;
    ra0 = *(const float4*)&A[(size_t)(m0 + a_r) * LL + a_c];
    ra1 = *(const float4*)&A[(size_t)(m0 + a_r + 64) * LL + a_c];
    rb0 = *(const float4*)&V[b_r * DH + b_c];

    int p = 0;
    *(uint4*)&As[0][a_r * AS_S + a_c]        = cvt4(ra0);
    *(uint4*)&As[0][(a_r + 64) * AS_S + a_c] = cvt4(ra1);
    *(uint4*)&Bs[0][b_r * BS64_S + b_c]      = cvt4(rb0);
    __syncthreads();

    for (int k0 = 16; k0 < LL; k0 += 16) {
        ra0 = *(const float4*)&A[(size_t)(m0 + a_r) * LL + k0 + a_c];
        ra1 = *(const float4*)&A[(size_t)(m0 + a_r + 64) * LL + k0 + a_c];
        rb0 = *(const float4*)&V[(k0 + b_r) * DH + b_c];

        #pragma unroll
        for (int kk = 0; kk < 16; kk += 8) {
            unsigned af[2][4], bf[4][2];
            #pragma unroll
            for (int mf = 0; mf < 2; mf++) {
                int row = wm + mf * 16 + g;
                af[mf][0] = As[p][row * AS_S + kk + tg];
                af[mf][1] = As[p][(row + 8) * AS_S + kk + tg];
                af[mf][2] = As[p][row * AS_S + kk + 4 + tg];
                af[mf][3] = As[p][(row + 8) * AS_S + kk + 4 + tg];
            }
            #pragma unroll
            for (int nf = 0; nf < 4; nf++) {
                int col = wn + nf * 8 + g;
                bf[nf][0] = Bs[p][(kk + tg) * BS64_S + col];
                bf[nf][1] = Bs[p][(kk + 4 + tg) * BS64_S + col];
            }
            #pragma unroll
            for (int mf = 0; mf < 2; mf++)
                #pragma unroll
                for (int nf = 0; nf < 4; nf++)
                    mma8(acc[mf][nf], af[mf], bf[nf], acc[mf][nf]);
        }

        int q = p ^ 1;
        *(uint4*)&As[q][a_r * AS_S + a_c]        = cvt4(ra0);
        *(uint4*)&As[q][(a_r + 64) * AS_S + a_c] = cvt4(ra1);
        *(uint4*)&Bs[q][b_r * BS64_S + b_c]      = cvt4(rb0);
        __syncthreads();
        p = q;
    }

    #pragma unroll
    for (int kk = 0; kk < 16; kk += 8) {
        unsigned af[2][4], bf[4][2];
        #pragma unroll
        for (int mf = 0; mf < 2; mf++) {
            int row = wm + mf * 16 + g;
            af[mf][0] = As[p][row * AS_S + kk + tg];
            af[mf][1] = As[p][(row + 8) * AS_S + kk + tg];
            af[mf][2] = As[p][row * AS_S + kk + 4 + tg];
            af[mf][3] = As[p][(row + 8) * AS_S + kk + 4 + tg];
        }
        #pragma unroll
        for (int nf = 0; nf < 4; nf++) {
            int col = wn + nf * 8 + g;
            bf[nf][0] = Bs[p][(kk + tg) * BS64_S + col];
            bf[nf][1] = Bs[p][(kk + 4 + tg) * BS64_S + col];
        }
        #pragma unroll
        for (int mf = 0; mf < 2; mf++)
            #pragma unroll
            for (int nf = 0; nf < 4; nf++)
                mma8(acc[mf][nf], af[mf], bf[nf], acc[mf][nf]);
    }

    int b = bh >> 4, h = bh & 15;
    #pragma unroll
    for (int mf = 0; mf < 2; mf++)
        #pragma unroll
        for (int nf = 0; nf < 4; nf++) {
            int n = wn + nf * 8 + 2 * tg;
            #pragma unroll
            for (int rr = 0; rr < 2; rr++) {
                int l = m0 + wm + mf * 16 + g + rr * 8;
                *(float2*)&g_ctx[((b * LL + l) * DD) + h * DH + n] =
                    make_float2(acc[mf][nf][rr * 2], acc[mf][nf][rr * 2 + 1]);
            }
        }
}

// ---------------------------------------------------------------------------
extern "C" void kernel_launch(void* const* d_in, const int* in_sizes, int n_in,
                              void* d_out, int out_size)
{
    const float* key   = (const float*)d_in[0];
    const float* value = (const float*)d_in[1];
    const float* query = (const float*)d_in[2];
    const int*   mat   = (const int*)d_in[3];
    const unsigned char* mask = (const unsigned char*)d_in[4];
    const float* Wq = (const float*)d_in[5];
    const float* bq = (const float*)d_in[6];
    const float* Wk = (const float*)d_in[7];
    const float* bk = (const float*)d_in[8];
    const float* Wv = (const float*)d_in[9];
    const float* bv = (const float*)d_in[10];
    const float* Wo = (const float*)d_in[11];
    const float* bo = (const float*)d_in[12];
    const float* semb = (const float*)d_in[13];
    const float* vemb = (const float*)d_in[14];

    float* out  = (float*)d_out;
    float* attn = out + OUT_ELEMS;   // scores buffer, softmaxed in place

    float *q, *k, *v, *ctx;
    cudaGetSymbolAddress((void**)&q,   g_q);
    cudaGetSymbolAddress((void**)&k,   g_k);
    cudaGetSymbolAddress((void**)&v,   g_v);
    cudaGetSymbolAddress((void**)&ctx, g_ctx);

    // Merged Q/K/V projection: one launch, 384 blocks
    PArgs qkv;
    qkv.p[0] = { query, Wq, bq, q, 0.125f, 1 };
    qkv.p[1] = { key,   Wk, bk, k, 1.0f,   2 };
    qkv.p[2] = { value, Wv, bv, v, 1.0f,   1 };
    proj_tf32<<<dim3(8, 16, 3), 256>>>(qkv);

    qk_tf32<<<dim3(4, 4, BH), 256>>>(attn);
    ast_tf32<<<dim3(LL, BB), 128>>>(mat, semb, vemb, attn);
    softmax_kernel<<<BH * LL, 128>>>(attn, mask);
    av_tf32<<<dim3(4, BH), 256>>>(attn);

    PArgs oarg;
    oarg.p[0] = { ctx, Wo, bo, out, 1.0f, 0 };
    oarg.p[1] = oarg.p[0];
    oarg.p[2] = oarg.p[0];
    proj_tf32<<<dim3(8, 16, 1), 256>>>(oarg);
}

// round 6
// speedup vs baseline: 2.8457x; 1.0238x over previous
#include <cuda_runtime.h>

// Problem constants
#define BB 4
#define LL 512
#define DD 1024
#define HH 16
#define DH 64
#define BH (BB*HH)            // 64
#define OUT_ELEMS (BB*LL*DD)  // 2097152

// Scratch (no allocations allowed -> __device__ globals)
__device__ float g_q[BB*HH*LL*DH];    // [b][h][l][dh]
__device__ float g_k[BB*HH*LL*DH];    // [b][h][dh][l]  (transposed for qk)
__device__ float g_v[BB*HH*LL*DH];    // [b][h][l][dh]
__device__ float g_ctx[BB*LL*DD];

// ---------------------------------------------------------------------------
// tf32 helpers (mma.sync m16n8k8, row.col, f32 accum)
// ---------------------------------------------------------------------------
__device__ __forceinline__ unsigned f2tf(float x) {
    unsigned y; asm("cvt.rna.tf32.f32 %0, %1;" : "=r"(y) : "f"(x)); return y;
}
__device__ __forceinline__ uint4 cvt4(float4 v) {
    uint4 u; u.x = f2tf(v.x); u.y = f2tf(v.y); u.z = f2tf(v.z); u.w = f2tf(v.w);
    return u;
}
__device__ __forceinline__ void mma8(float* d, const unsigned* a,
                                     const unsigned* b, const float* c) {
    asm volatile(
        "mma.sync.aligned.m16n8k8.row.col.f32.tf32.tf32.f32 "
        "{%0,%1,%2,%3}, {%4,%5,%6,%7}, {%8,%9}, {%10,%11,%12,%13};"
        : "=f"(d[0]), "=f"(d[1]), "=f"(d[2]), "=f"(d[3])
        : "r"(a[0]), "r"(a[1]), "r"(a[2]), "r"(a[3]),
          "r"(b[0]), "r"(b[1]),
          "f"(c[0]), "f"(c[1]), "f"(c[2]), "f"(c[3]));
}

// Smem strides chosen conflict-free:
//   As stride 20  (20 mod 32 = 4  -> frag banks 4g+tg = lane, all distinct)
//   Bs stride 136 (136 mod 32 = 8 -> frag banks 8tg+g, all distinct, g<8)
//   Bs64 stride 72 (72 mod 32 = 8)
#define AS_S 20
#define BS_S 136
#define BS64_S 72

struct PArg { const float* A; const float* W; const float* bias;
              float* out; float scale; int mode; };
struct PArgs { PArg p[3]; };

// ---------------------------------------------------------------------------
// Projection GEMM: C = A(2048x1024) @ W(1024x1024) + bias, scale.
// mode 0: out[m][n]; mode 1: [b][h][l][dh]; mode 2: [b][h][dh][l].
// Tile 128x128, BK=16, 2-stage smem double buffer + register prefetch.
// 8 warps (2m x 4n), warp tile 64x32. blockIdx.z selects the projection.
// ---------------------------------------------------------------------------
__global__ __launch_bounds__(256, 2) void proj_tf32(PArgs args)
{
    __shared__ __align__(16) unsigned As[2][128 * AS_S];
    __shared__ __align__(16) unsigned Bs[2][16 * BS_S];
    const int K = 1024, N = 1024;

    PArg pa = args.p[blockIdx.z];
    const float* __restrict__ A = pa.A;
    const float* __restrict__ W = pa.W;

    int t = threadIdx.x;
    int m0 = blockIdx.y * 128, n0 = blockIdx.x * 128;
    int wid = t >> 5, lane = t & 31;
    int wm = (wid >> 2) * 64, wn = (wid & 3) * 32;
    int g = lane >> 2, tg = lane & 3;

    int a_r = t >> 2;            // 0..63 (+64)
    int a_c = (t & 3) * 4;
    int b_r = t >> 5;            // 0..7 (+8)
    int b_c = (t & 31) * 4;

    float acc[4][4][4];
    #pragma unroll
    for (int i = 0; i < 4; i++)
        #pragma unroll
        for (int j = 0; j < 4; j++)
            #pragma unroll
            for (int e = 0; e < 4; e++) acc[i][j][e] = 0.f;

    float4 ra0, ra1, rb0, rb1;
    ra0 = *(const float4*)&A[(m0 + a_r) * K + a_c];
    ra1 = *(const float4*)&A[(m0 + a_r + 64) * K + a_c];
    rb0 = *(const float4*)&W[b_r * N + n0 + b_c];
    rb1 = *(const float4*)&W[(b_r + 8) * N + n0 + b_c];

    int p = 0;
    *(uint4*)&As[0][a_r * AS_S + a_c]        = cvt4(ra0);
    *(uint4*)&As[0][(a_r + 64) * AS_S + a_c] = cvt4(ra1);
    *(uint4*)&Bs[0][b_r * BS_S + b_c]        = cvt4(rb0);
    *(uint4*)&Bs[0][(b_r + 8) * BS_S + b_c]  = cvt4(rb1);
    __syncthreads();

    for (int k0 = 16; k0 < K; k0 += 16) {
        ra0 = *(const float4*)&A[(m0 + a_r) * K + k0 + a_c];
        ra1 = *(const float4*)&A[(m0 + a_r + 64) * K + k0 + a_c];
        rb0 = *(const float4*)&W[(k0 + b_r) * N + n0 + b_c];
        rb1 = *(const float4*)&W[(k0 + b_r + 8) * N + n0 + b_c];

        #pragma unroll
        for (int kk = 0; kk < 16; kk += 8) {
            unsigned af[4][4], bf[4][2];
            #pragma unroll
            for (int mf = 0; mf < 4; mf++) {
                int row = wm + mf * 16 + g;
                af[mf][0] = As[p][row * AS_S + kk + tg];
                af[mf][1] = As[p][(row + 8) * AS_S + kk + tg];
                af[mf][2] = As[p][row * AS_S + kk + 4 + tg];
                af[mf][3] = As[p][(row + 8) * AS_S + kk + 4 + tg];
            }
            #pragma unroll
            for (int nf = 0; nf < 4; nf++) {
                int col = wn + nf * 8 + g;
                bf[nf][0] = Bs[p][(kk + tg) * BS_S + col];
                bf[nf][1] = Bs[p][(kk + 4 + tg) * BS_S + col];
            }
            #pragma unroll
            for (int mf = 0; mf < 4; mf++)
                #pragma unroll
                for (int nf = 0; nf < 4; nf++)
                    mma8(acc[mf][nf], af[mf], bf[nf], acc[mf][nf]);
        }

        int q = p ^ 1;
        *(uint4*)&As[q][a_r * AS_S + a_c]        = cvt4(ra0);
        *(uint4*)&As[q][(a_r + 64) * AS_S + a_c] = cvt4(ra1);
        *(uint4*)&Bs[q][b_r * BS_S + b_c]        = cvt4(rb0);
        *(uint4*)&Bs[q][(b_r + 8) * BS_S + b_c]  = cvt4(rb1);
        __syncthreads();
        p = q;
    }

    // last tile
    #pragma unroll
    for (int kk = 0; kk < 16; kk += 8) {
        unsigned af[4][4], bf[4][2];
        #pragma unroll
        for (int mf = 0; mf < 4; mf++) {
            int row = wm + mf * 16 + g;
            af[mf][0] = As[p][row * AS_S + kk + tg];
            af[mf][1] = As[p][(row + 8) * AS_S + kk + tg];
            af[mf][2] = As[p][row * AS_S + kk + 4 + tg];
            af[mf][3] = As[p][(row + 8) * AS_S + kk + 4 + tg];
        }
        #pragma unroll
        for (int nf = 0; nf < 4; nf++) {
            int col = wn + nf * 8 + g;
            bf[nf][0] = Bs[p][(kk + tg) * BS_S + col];
            bf[nf][1] = Bs[p][(kk + 4 + tg) * BS_S + col];
        }
        #pragma unroll
        for (int mf = 0; mf < 4; mf++)
            #pragma unroll
            for (int nf = 0; nf < 4; nf++)
                mma8(acc[mf][nf], af[mf], bf[nf], acc[mf][nf]);
    }

    #pragma unroll
    for (int mf = 0; mf < 4; mf++) {
        #pragma unroll
        for (int nf = 0; nf < 4; nf++) {
            int col = n0 + wn + nf * 8 + 2 * tg;
            float2 b2 = *(const float2*)&pa.bias[col];
            #pragma unroll
            for (int rr = 0; rr < 2; rr++) {
                int m = m0 + wm + mf * 16 + g + rr * 8;
                float vx = (acc[mf][nf][rr * 2 + 0] + b2.x) * pa.scale;
                float vy = (acc[mf][nf][rr * 2 + 1] + b2.y) * pa.scale;
                if (pa.mode == 0) {
                    *(float2*)&pa.out[m * 1024 + col] = make_float2(vx, vy);
                } else {
                    int b = m >> 9, l = m & 511;
                    int h = col >> 6, dh = col & 63;
                    if (pa.mode == 1) {
                        *(float2*)&pa.out[((b * HH + h) * LL + l) * DH + dh] =
                            make_float2(vx, vy);
                    } else {
                        pa.out[((b * HH + h) * DH + dh) * LL + l] = vx;
                        pa.out[((b * HH + h) * DH + dh + 1) * LL + l] = vy;
                    }
                }
            }
        }
    }
}

// ---------------------------------------------------------------------------
// qk: scores[bh][i][j] = q[bh][i][:] . kT[bh][:][j]  (M=N=512, K=64 per bh)
// ---------------------------------------------------------------------------
__global__ __launch_bounds__(256, 2) void qk_tf32(float* __restrict__ scores)
{
    __shared__ __align__(16) unsigned As[2][128 * AS_S];
    __shared__ __align__(16) unsigned Bs[2][16 * BS_S];

    int t = threadIdx.x;
    int bh = blockIdx.z;
    const float* __restrict__ Q  = g_q + bh * LL * DH;   // [l][dh]
    const float* __restrict__ KT = g_k + bh * LL * DH;   // [dh][l]
    int m0 = blockIdx.y * 128, n0 = blockIdx.x * 128;
    int wid = t >> 5, lane = t & 31;
    int wm = (wid >> 2) * 64, wn = (wid & 3) * 32;
    int g = lane >> 2, tg = lane & 3;

    int a_r = t >> 2, a_c = (t & 3) * 4;
    int b_r = t >> 5, b_c = (t & 31) * 4;

    float acc[4][4][4];
    #pragma unroll
    for (int i = 0; i < 4; i++)
        #pragma unroll
        for (int j = 0; j < 4; j++)
            #pragma unroll
            for (int e = 0; e < 4; e++) acc[i][j][e] = 0.f;

    float4 ra0, ra1, rb0, rb1;
    ra0 = *(const float4*)&Q[(m0 + a_r) * DH + a_c];
    ra1 = *(const float4*)&Q[(m0 + a_r + 64) * DH + a_c];
    rb0 = *(const float4*)&KT[b_r * LL + n0 + b_c];
    rb1 = *(const float4*)&KT[(b_r + 8) * LL + n0 + b_c];

    int p = 0;
    *(uint4*)&As[0][a_r * AS_S + a_c]        = cvt4(ra0);
    *(uint4*)&As[0][(a_r + 64) * AS_S + a_c] = cvt4(ra1);
    *(uint4*)&Bs[0][b_r * BS_S + b_c]        = cvt4(rb0);
    *(uint4*)&Bs[0][(b_r + 8) * BS_S + b_c]  = cvt4(rb1);
    __syncthreads();

    for (int k0 = 16; k0 < DH; k0 += 16) {
        ra0 = *(const float4*)&Q[(m0 + a_r) * DH + k0 + a_c];
        ra1 = *(const float4*)&Q[(m0 + a_r + 64) * DH + k0 + a_c];
        rb0 = *(const float4*)&KT[(k0 + b_r) * LL + n0 + b_c];
        rb1 = *(const float4*)&KT[(k0 + b_r + 8) * LL + n0 + b_c];

        #pragma unroll
        for (int kk = 0; kk < 16; kk += 8) {
            unsigned af[4][4], bf[4][2];
            #pragma unroll
            for (int mf = 0; mf < 4; mf++) {
                int row = wm + mf * 16 + g;
                af[mf][0] = As[p][row * AS_S + kk + tg];
                af[mf][1] = As[p][(row + 8) * AS_S + kk + tg];
                af[mf][2] = As[p][row * AS_S + kk + 4 + tg];
                af[mf][3] = As[p][(row + 8) * AS_S + kk + 4 + tg];
            }
            #pragma unroll
            for (int nf = 0; nf < 4; nf++) {
                int col = wn + nf * 8 + g;
                bf[nf][0] = Bs[p][(kk + tg) * BS_S + col];
                bf[nf][1] = Bs[p][(kk + 4 + tg) * BS_S + col];
            }
            #pragma unroll
            for (int mf = 0; mf < 4; mf++)
                #pragma unroll
                for (int nf = 0; nf < 4; nf++)
                    mma8(acc[mf][nf], af[mf], bf[nf], acc[mf][nf]);
        }

        int q = p ^ 1;
        *(uint4*)&As[q][a_r * AS_S + a_c]        = cvt4(ra0);
        *(uint4*)&As[q][(a_r + 64) * AS_S + a_c] = cvt4(ra1);
        *(uint4*)&Bs[q][b_r * BS_S + b_c]        = cvt4(rb0);
        *(uint4*)&Bs[q][(b_r + 8) * BS_S + b_c]  = cvt4(rb1);
        __syncthreads();
        p = q;
    }

    #pragma unroll
    for (int kk = 0; kk < 16; kk += 8) {
        unsigned af[4][4], bf[4][2];
        #pragma unroll
        for (int mf = 0; mf < 4; mf++) {
            int row = wm + mf * 16 + g;
            af[mf][0] = As[p][row * AS_S + kk + tg];
            af[mf][1] = As[p][(row + 8) * AS_S + kk + tg];
            af[mf][2] = As[p][row * AS_S + kk + 4 + tg];
            af[mf][3] = As[p][(row + 8) * AS_S + kk + 4 + tg];
        }
        #pragma unroll
        for (int nf = 0; nf < 4; nf++) {
            int col = wn + nf * 8 + g;
            bf[nf][0] = Bs[p][(kk + tg) * BS_S + col];
            bf[nf][1] = Bs[p][(kk + 4 + tg) * BS_S + col];
        }
        #pragma unroll
        for (int mf = 0; mf < 4; mf++)
            #pragma unroll
            for (int nf = 0; nf < 4; nf++)
                mma8(acc[mf][nf], af[mf], bf[nf], acc[mf][nf]);
    }

    float* srow = scores + (size_t)bh * LL * LL;
    #pragma unroll
    for (int mf = 0; mf < 4; mf++)
        #pragma unroll
        for (int nf = 0; nf < 4; nf++) {
            int col = n0 + wn + nf * 8 + 2 * tg;
            #pragma unroll
            for (int rr = 0; rr < 2; rr++) {
                int m = m0 + wm + mf * 16 + g + rr * 8;
                *(float2*)&srow[m * LL + col] =
                    make_float2(acc[mf][nf][rr * 2], acc[mf][nf][rr * 2 + 1]);
            }
        }
}

// ---------------------------------------------------------------------------
// Fused ast + mask + softmax.
// Block (i, b), 128 threads. Computes score_ast via tf32 MMA, keeps all
// 16h x 512j scores for row i in registers (64/thread), adds the qk scores
// from gmem, applies mask, does an in-register softmax (tg-shfl + smem
// cross-warp reduction), and writes the final attn rows once.
// Thread (wid, g, tg) owns rows h=g and h=g+8, cols jt*128+wid*32+nf*8+2tg+{0,1}.
// ---------------------------------------------------------------------------
__global__ __launch_bounds__(128) void astsm_tf32(
    const int* __restrict__ mat, const float* __restrict__ semb,
    const float* __restrict__ vemb, float* __restrict__ attn,
    const unsigned char* __restrict__ mask)
{
    __shared__ __align__(16) unsigned qs[16 * 68];
    __shared__ __align__(16) unsigned pe[128 * 68];
    __shared__ unsigned char mks[512];
    __shared__ float redmx[16 * 4];
    __shared__ float redsm[16 * 4];

    int i = blockIdx.x, b = blockIdx.y;
    int t = threadIdx.x;
    int wid = t >> 5, lane = t & 31;
    int g = lane >> 2, tg = lane & 3;

    for (int idx = t; idx < HH * DH; idx += 128) {
        int h = idx >> 6, d = idx & 63;
        qs[h * 68 + d] = f2tf(g_q[((b * HH + h) * LL + i) * DH + d]);
    }
    *(uchar4*)&mks[t * 4] = *(const uchar4*)&mask[b * LL + t * 4];
    __syncthreads();

    // Hoist A fragments (constant over j): 8 k-steps x 4 regs
    unsigned af[8][4];
    #pragma unroll
    for (int ks = 0; ks < 8; ks++) {
        af[ks][0] = qs[g * 68 + ks * 8 + tg];
        af[ks][1] = qs[(g + 8) * 68 + ks * 8 + tg];
        af[ks][2] = qs[g * 68 + ks * 8 + 4 + tg];
        af[ks][3] = qs[(g + 8) * 68 + ks * 8 + 4 + tg];
    }

    const int* mrow = mat + (b * LL + i) * LL;
    float sc[4][4][4];   // [jt][nf][e]

    for (int jt = 0; jt < 4; jt++) {
        int j0 = jt * 128;
        __syncthreads();   // pe reuse across jt
        {
            int j = j0 + t;
            int id = mrow[j];
            const float* e = ((j & 1) ? vemb : semb) + id * DH;
            #pragma unroll
            for (int s = 0; s < 64; s += 4)
                *(uint4*)&pe[t * 68 + s] = cvt4(*(const float4*)&e[s]);
        }
        __syncthreads();

        #pragma unroll
        for (int nf = 0; nf < 4; nf++)
            #pragma unroll
            for (int e = 0; e < 4; e++) sc[jt][nf][e] = 0.f;

        #pragma unroll
        for (int ks = 0; ks < 8; ks++) {
            #pragma unroll
            for (int nf = 0; nf < 4; nf++) {
                int jj = wid * 32 + nf * 8 + g;
                unsigned bf[2];
                bf[0] = pe[jj * 68 + ks * 8 + tg];
                bf[1] = pe[jj * 68 + ks * 8 + 4 + tg];
                mma8(sc[jt][nf], af[ks], bf, sc[jt][nf]);
            }
        }
    }

    // Add qk scores and apply mask
    size_t base0 = (((size_t)(b * HH + g) * LL + i) * LL);
    size_t base1 = (((size_t)(b * HH + g + 8) * LL + i) * LL);
    #pragma unroll
    for (int jt = 0; jt < 4; jt++)
        #pragma unroll
        for (int nf = 0; nf < 4; nf++) {
            int col = jt * 128 + wid * 32 + nf * 8 + 2 * tg;
            float2 s0 = *(const float2*)&attn[base0 + col];
            float2 s1 = *(const float2*)&attn[base1 + col];
            sc[jt][nf][0] += s0.x; sc[jt][nf][1] += s0.y;
            sc[jt][nf][2] += s1.x; sc[jt][nf][3] += s1.y;
            if (mks[col])     { sc[jt][nf][0] = -1e18f; sc[jt][nf][2] = -1e18f; }
            if (mks[col + 1]) { sc[jt][nf][1] = -1e18f; sc[jt][nf][3] = -1e18f; }
        }

    // Row max (rows g and g+8)
    float mx0 = -1e30f, mx1 = -1e30f;
    #pragma unroll
    for (int jt = 0; jt < 4; jt++)
        #pragma unroll
        for (int nf = 0; nf < 4; nf++) {
            mx0 = fmaxf(mx0, fmaxf(sc[jt][nf][0], sc[jt][nf][1]));
            mx1 = fmaxf(mx1, fmaxf(sc[jt][nf][2], sc[jt][nf][3]));
        }
    // reduce over tg (lane = g*4+tg -> xor 1,2 keeps g)
    #pragma unroll
    for (int o = 1; o <= 2; o <<= 1) {
        mx0 = fmaxf(mx0, __shfl_xor_sync(0xffffffffu, mx0, o));
        mx1 = fmaxf(mx1, __shfl_xor_sync(0xffffffffu, mx1, o));
    }
    if (tg == 0) { redmx[g * 4 + wid] = mx0; redmx[(g + 8) * 4 + wid] = mx1; }
    __syncthreads();
    mx0 = fmaxf(fmaxf(redmx[g * 4 + 0], redmx[g * 4 + 1]),
                fmaxf(redmx[g * 4 + 2], redmx[g * 4 + 3]));
    mx1 = fmaxf(fmaxf(redmx[(g + 8) * 4 + 0], redmx[(g + 8) * 4 + 1]),
                fmaxf(redmx[(g + 8) * 4 + 2], redmx[(g + 8) * 4 + 3]));

    // exp + row sum
    float sm0 = 0.f, sm1 = 0.f;
    #pragma unroll
    for (int jt = 0; jt < 4; jt++)
        #pragma unroll
        for (int nf = 0; nf < 4; nf++) {
            sc[jt][nf][0] = __expf(sc[jt][nf][0] - mx0);
            sc[jt][nf][1] = __expf(sc[jt][nf][1] - mx0);
            sc[jt][nf][2] = __expf(sc[jt][nf][2] - mx1);
            sc[jt][nf][3] = __expf(sc[jt][nf][3] - mx1);
            sm0 += sc[jt][nf][0] + sc[jt][nf][1];
            sm1 += sc[jt][nf][2] + sc[jt][nf][3];
        }
    #pragma unroll
    for (int o = 1; o <= 2; o <<= 1) {
        sm0 += __shfl_xor_sync(0xffffffffu, sm0, o);
        sm1 += __shfl_xor_sync(0xffffffffu, sm1, o);
    }
    if (tg == 0) { redsm[g * 4 + wid] = sm0; redsm[(g + 8) * 4 + wid] = sm1; }
    __syncthreads();
    sm0 = redsm[g * 4 + 0] + redsm[g * 4 + 1] + redsm[g * 4 + 2] + redsm[g * 4 + 3];
    sm1 = redsm[(g + 8) * 4 + 0] + redsm[(g + 8) * 4 + 1] +
          redsm[(g + 8) * 4 + 2] + redsm[(g + 8) * 4 + 3];
    float inv0 = 1.0f / sm0, inv1 = 1.0f / sm1;

    // Write final attn
    #pragma unroll
    for (int jt = 0; jt < 4; jt++)
        #pragma unroll
        for (int nf = 0; nf < 4; nf++) {
            int col = jt * 128 + wid * 32 + nf * 8 + 2 * tg;
            *(float2*)&attn[base0 + col] =
                make_float2(sc[jt][nf][0] * inv0, sc[jt][nf][1] * inv0);
            *(float2*)&attn[base1 + col] =
                make_float2(sc[jt][nf][2] * inv1, sc[jt][nf][3] * inv1);
        }
}

// ---------------------------------------------------------------------------
// av: ctx[b][l][h*64+d] = sum_j attn[bh][l][j] * v[bh][j][d]
// Per bh: M=512 N=64 K=512. Tile 128x64, BK=16, 2-stage pipeline.
// ---------------------------------------------------------------------------
__global__ __launch_bounds__(256, 2) void av_tf32(const float* __restrict__ attn)
{
    __shared__ __align__(16) unsigned As[2][128 * AS_S];
    __shared__ __align__(16) unsigned Bs[2][16 * BS64_S];

    int t = threadIdx.x;
    int bh = blockIdx.y;
    int m0 = blockIdx.x * 128;
    const float* __restrict__ A = attn + (size_t)bh * LL * LL;
    const float* __restrict__ V = g_v + bh * LL * DH;
    int wid = t >> 5, lane = t & 31;
    int wm = (wid >> 1) * 32, wn = (wid & 1) * 32;
    int g = lane >> 2, tg = lane & 3;

    int a_r = t >> 2, a_c = (t & 3) * 4;
    int b_r = t >> 4, b_c = (t & 15) * 4;

    float acc[2][4][4];
    #pragma unroll
    for (int i = 0; i < 2; i++)
        #pragma unroll
        for (int j = 0; j < 4; j++)
            #pragma unroll
            for (int e = 0; e < 4; e++) acc[i][j][e] = 0.f;

    float4 ra0, ra1, rb0;
    ra0 = *(const float4*)&A[(size_t)(m0 + a_r) * LL + a_c];
    ra1 = *(const float4*)&A[(size_t)(m0 + a_r + 64) * LL + a_c];
    rb0 = *(const float4*)&V[b_r * DH + b_c];

    int p = 0;
    *(uint4*)&As[0][a_r * AS_S + a_c]        = cvt4(ra0);
    *(uint4*)&As[0][(a_r + 64) * AS_S + a_c] = cvt4(ra1);
    *(uint4*)&Bs[0][b_r * BS64_S + b_c]      = cvt4(rb0);
    __syncthreads();

    for (int k0 = 16; k0 < LL; k0 += 16) {
        ra0 = *(const float4*)&A[(size_t)(m0 + a_r) * LL + k0 + a_c];
        ra1 = *(const float4*)&A[(size_t)(m0 + a_r + 64) * LL + k0 + a_c];
        rb0 = *(const float4*)&V[(k0 + b_r) * DH + b_c];

        #pragma unroll
        for (int kk = 0; kk < 16; kk += 8) {
            unsigned af[2][4], bf[4][2];
            #pragma unroll
            for (int mf = 0; mf < 2; mf++) {
                int row = wm + mf * 16 + g;
                af[mf][0] = As[p][row * AS_S + kk + tg];
                af[mf][1] = As[p][(row + 8) * AS_S + kk + tg];
                af[mf][2] = As[p][row * AS_S + kk + 4 + tg];
                af[mf][3] = As[p][(row + 8) * AS_S + kk + 4 + tg];
            }
            #pragma unroll
            for (int nf = 0; nf < 4; nf++) {
                int col = wn + nf * 8 + g;
                bf[nf][0] = Bs[p][(kk + tg) * BS64_S + col];
                bf[nf][1] = Bs[p][(kk + 4 + tg) * BS64_S + col];
            }
            #pragma unroll
            for (int mf = 0; mf < 2; mf++)
                #pragma unroll
                for (int nf = 0; nf < 4; nf++)
                    mma8(acc[mf][nf], af[mf], bf[nf], acc[mf][nf]);
        }

        int q = p ^ 1;
        *(uint4*)&As[q][a_r * AS_S + a_c]        = cvt4(ra0);
        *(uint4*)&As[q][(a_r + 64) * AS_S + a_c] = cvt4(ra1);
        *(uint4*)&Bs[q][b_r * BS64_S + b_c]      = cvt4(rb0);
        __syncthreads();
        p = q;
    }

    #pragma unroll
    for (int kk = 0; kk < 16; kk += 8) {
        unsigned af[2][4], bf[4][2];
        #pragma unroll
        for (int mf = 0; mf < 2; mf++) {
            int row = wm + mf * 16 + g;
            af[mf][0] = As[p][row * AS_S + kk + tg];
            af[mf][1] = As[p][(row + 8) * AS_S + kk + tg];
            af[mf][2] = As[p][row * AS_S + kk + 4 + tg];
            af[mf][3] = As[p][(row + 8) * AS_S + kk + 4 + tg];
        }
        #pragma unroll
        for (int nf = 0; nf < 4; nf++) {
            int col = wn + nf * 8 + g;
            bf[nf][0] = Bs[p][(kk + tg) * BS64_S + col];
            bf[nf][1] = Bs[p][(kk + 4 + tg) * BS64_S + col];
        }
        #pragma unroll
        for (int mf = 0; mf < 2; mf++)
            #pragma unroll
            for (int nf = 0; nf < 4; nf++)
                mma8(acc[mf][nf], af[mf], bf[nf], acc[mf][nf]);
    }

    int b = bh >> 4, h = bh & 15;
    #pragma unroll
    for (int mf = 0; mf < 2; mf++)
        #pragma unroll
        for (int nf = 0; nf < 4; nf++) {
            int n = wn + nf * 8 + 2 * tg;
            #pragma unroll
            for (int rr = 0; rr < 2; rr++) {
                int l = m0 + wm + mf * 16 + g + rr * 8;
                *(float2*)&g_ctx[((b * LL + l) * DD) + h * DH + n] =
                    make_float2(acc[mf][nf][rr * 2], acc[mf][nf][rr * 2 + 1]);
            }
        }
}

// ---------------------------------------------------------------------------
extern "C" void kernel_launch(void* const* d_in, const int* in_sizes, int n_in,
                              void* d_out, int out_size)
{
    const float* key   = (const float*)d_in[0];
    const float* value = (const float*)d_in[1];
    const float* query = (const float*)d_in[2];
    const int*   mat   = (const int*)d_in[3];
    const unsigned char* mask = (const unsigned char*)d_in[4];
    const float* Wq = (const float*)d_in[5];
    const float* bq = (const float*)d_in[6];
    const float* Wk = (const float*)d_in[7];
    const float* bk = (const float*)d_in[8];
    const float* Wv = (const float*)d_in[9];
    const float* bv = (const float*)d_in[10];
    const float* Wo = (const float*)d_in[11];
    const float* bo = (const float*)d_in[12];
    const float* semb = (const float*)d_in[13];
    const float* vemb = (const float*)d_in[14];

    float* out  = (float*)d_out;
    float* attn = out + OUT_ELEMS;   // scores buffer, finalized in astsm

    float *q, *k, *v, *ctx;
    cudaGetSymbolAddress((void**)&q,   g_q);
    cudaGetSymbolAddress((void**)&k,   g_k);
    cudaGetSymbolAddress((void**)&v,   g_v);
    cudaGetSymbolAddress((void**)&ctx, g_ctx);

    // Merged Q/K/V projection: one launch, 384 blocks
    PArgs qkv;
    qkv.p[0] = { query, Wq, bq, q, 0.125f, 1 };
    qkv.p[1] = { key,   Wk, bk, k, 1.0f,   2 };
    qkv.p[2] = { value, Wv, bv, v, 1.0f,   1 };
    proj_tf32<<<dim3(8, 16, 3), 256>>>(qkv);

    qk_tf32<<<dim3(4, 4, BH), 256>>>(attn);
    astsm_tf32<<<dim3(LL, BB), 128>>>(mat, semb, vemb, attn, mask);
    av_tf32<<<dim3(4, BH), 256>>>(attn);

    PArgs oarg;
    oarg.p[0] = { ctx, Wo, bo, out, 1.0f, 0 };
    oarg.p[1] = oarg.p[0];
    oarg.p[2] = oarg.p[0];
    proj_tf32<<<dim3(8, 16, 1), 256>>>(oarg);
}